// round 12
// baseline (speedup 1.0000x reference)
#include <cuda_runtime.h>
#include <cuda_bf16.h>
#include <cstdint>

constexpr int BSZ = 8192;
constexpr int HH  = 2048;
constexpr int DD  = 104;
constexpr int DP  = 128;                      // padded D for uniform K loop

// bf16 scratch (device globals — no dynamic allocation)
__device__ __nv_bfloat16 g_hid[(size_t)BSZ * HH];    // 33.5 MB
__device__ __nv_bfloat16 g_Uw [(size_t)HH  * HH];    //  8.4 MB
__device__ __nv_bfloat16 g_line[(size_t)BSZ * DP];   //  2.1 MB (zero-padded)
__device__ __nv_bfloat16 g_Ww [(size_t)HH  * DP];    //  0.5 MB (zero-padded)
__device__ __nv_bfloat16 g_htb[(size_t)BSZ * HH];    // 33.5 MB (h_t in bf16)
__device__ __nv_bfloat16 g_Vwb[(size_t)DD  * HH];    //  0.4 MB

static __device__ __forceinline__ uint32_t s2u(const void* p) {
    uint32_t a;
    asm("{ .reg .u64 t; cvta.to.shared.u64 t, %1; cvt.u32.u64 %0, t; }"
        : "=r"(a) : "l"(p));
    return a;
}

#define LDSM4(r0, r1, r2, r3, addr)                                          \
    asm volatile("ldmatrix.sync.aligned.m8n8.x4.shared.b16 {%0,%1,%2,%3}, [%4];" \
                 : "=r"(r0), "=r"(r1), "=r"(r2), "=r"(r3) : "r"(addr))

static __device__ __forceinline__ void mma16(float c[4], const uint32_t a[4],
                                             uint32_t b0, uint32_t b1) {
    asm volatile(
        "mma.sync.aligned.m16n8k16.row.col.f32.bf16.bf16.f32 "
        "{%0,%1,%2,%3}, {%4,%5,%6,%7}, {%8,%9}, {%0,%1,%2,%3};\n"
        : "+f"(c[0]), "+f"(c[1]), "+f"(c[2]), "+f"(c[3])
        : "r"(a[0]), "r"(a[1]), "r"(a[2]), "r"(a[3]), "r"(b0), "r"(b1));
}

#define CPA16(dst, src) \
    asm volatile("cp.async.cg.shared.global [%0], [%1], 16;" :: "r"(dst), "l"(src) : "memory")
#define CPA_COMMIT() asm volatile("cp.async.commit_group;" ::: "memory")
#define CPA_WAIT(n)  asm volatile("cp.async.wait_group %0;" :: "n"(n) : "memory")

static __device__ __forceinline__ float sigmoidf_(float x) {
    return 1.0f / (1.0f + __expf(-x));
}
static __device__ __forceinline__ uint32_t packbf2(float x, float y) {
    __nv_bfloat162 h = __floats2bfloat162_rn(x, y);
    return *(uint32_t*)&h;
}

// ============================================================================
// Single fused convert kernel: hidden -> g_hid, U_w -> g_Uw, V_w -> g_Vwb
// (float4 jobs), then line/W_w -> zero-padded bf16 (scalar job).
// ============================================================================
constexpr size_t NH4   = (size_t)BSZ * HH / 4;       // 4194304
constexpr size_t NU4   = (size_t)HH  * HH / 4;       // 1048576
constexpr size_t NV4   = (size_t)DD  * HH / 4;       // 53248
constexpr size_t NF4   = NH4 + NU4 + NV4;            // float4 jobs
constexpr size_t NPAD  = (size_t)(BSZ + HH) * DP;    // scalar pad job
constexpr size_t NCVT  = NF4 + NPAD;

__global__ __launch_bounds__(256) void cvt_all(
    const float4* __restrict__ hid, const float4* __restrict__ uw,
    const float4* __restrict__ vw,  const float*  __restrict__ line,
    const float*  __restrict__ ww)
{
    size_t i = (size_t)blockIdx.x * blockDim.x + threadIdx.x;
    if (i >= NCVT) return;
    if (i < NF4) {
        float4 v; __nv_bfloat16* dst;
        if (i < NH4)            { v = hid[i];              dst = g_hid + i * 4; }
        else if (i < NH4 + NU4) { v = uw[i - NH4];         dst = g_Uw  + (i - NH4) * 4; }
        else                    { v = vw[i - NH4 - NU4];   dst = g_Vwb + (i - NH4 - NU4) * 4; }
        uint2 o;
        o.x = packbf2(v.x, v.y);
        o.y = packbf2(v.z, v.w);
        *(uint2*)dst = o;
    } else {
        size_t j   = i - NF4;
        size_t row = j >> 7;
        int    col = (int)(j & 127);
        float v = 0.f;
        if (col < DD)
            v = (row < BSZ) ? line[row * DD + col] : ww[(row - BSZ) * DD + col];
        ((row < BSZ) ? g_line : g_Ww)[((row < BSZ) ? row : row - BSZ) * DP + col] =
            __float2bfloat16(v);
    }
}

// ============================================================================
// Kernel 1 — EXACT Round-5 configuration (best measured: 346 us, regs=106):
// CTA 128x128, BK=32, 256 thr, 2x4 warp grid, 64x32 warp tiles, 2 CTAs/SM,
// 4-stage cp.async (WAIT(2)), single barrier per iter, refill before compute.
// ============================================================================
constexpr int RS      = 40;                   // smem row stride, bf16 elems (80B)
constexpr int OP_B    = 128 * RS * 2;         // 10240 B per operand per stage
constexpr int STG     = 2 * OP_B;             // 20480 B per stage
constexpr int K1_ST   = 4;
constexpr int K1_SMEM = K1_ST * STG;          // 81920
constexpr int K1_NT1  = HH / 32;              // 64
constexpr int K1_NT   = K1_NT1 + DP / 32;     // 68

__global__ __launch_bounds__(256) void rnn_k1(
    const float* __restrict__ U_b, const float* __restrict__ W_b,
    float* __restrict__ ht)
{
    extern __shared__ char sm1[];
    const uint32_t sb = s2u(sm1);

    const int tid  = threadIdx.x;
    const int warp = tid >> 5, lane = tid & 31;
    const int wm   = (warp >> 2) * 64;
    const int wn   = (warp & 3) * 32;
    const int grp  = lane >> 2, tig = lane & 3;
    const int lr16 = lane & 15, lh = lane >> 4;

    const int mBase = blockIdx.y * 128;
    const int nBase = blockIdx.x * 128;

    uint32_t aOff[4], bOff[2];
    #pragma unroll
    for (int mt = 0; mt < 4; mt++)
        aOff[mt] = ((wm + mt * 16 + lr16) * RS + lh * 8) * 2;
    #pragma unroll
    for (int p = 0; p < 2; p++)
        bOff[p] = OP_B + ((wn + p * 16 + lr16) * RS + lh * 8) * 2;

    // producer: thread owns row tid>>1, 32B chunk pair at col (tid&1)*16
    const int lrow = tid >> 1;
    const int lcb  = (tid & 1) * 16;
    const __nv_bfloat16* hA = g_hid  + (size_t)(mBase + lrow) * HH + lcb;
    const __nv_bfloat16* uB = g_Uw   + (size_t)(nBase + lrow) * HH + lcb;
    const __nv_bfloat16* lA = g_line + (size_t)(mBase + lrow) * DP + lcb;
    const __nv_bfloat16* wB = g_Ww   + (size_t)(nBase + lrow) * DP + lcb;
    const uint32_t dOff = (uint32_t)(lrow * RS + lcb) * 2;

    auto issue_stage = [&](int slot, int f) {
        const uint32_t dA = sb + slot * STG + dOff;
        const uint32_t dB = dA + OP_B;
        const __nv_bfloat16 *sA, *sB;
        if (f < K1_NT1) { sA = hA + f * 32;             sB = uB + f * 32; }
        else            { sA = lA + (f - K1_NT1) * 32;  sB = wB + (f - K1_NT1) * 32; }
        CPA16(dA,      sA);
        CPA16(dA + 16, sA + 8);
        CPA16(dB,      sB);
        CPA16(dB + 16, sB + 8);
    };

    float acc[4][4][4];
    #pragma unroll
    for (int i = 0; i < 4; i++)
        #pragma unroll
        for (int j = 0; j < 4; j++)
            #pragma unroll
            for (int k = 0; k < 4; k++) acc[i][j][k] = 0.f;

    #pragma unroll
    for (int s = 0; s < K1_ST - 1; s++) { issue_stage(s, s); CPA_COMMIT(); }

    for (int t = 0; t < K1_NT; t++) {
        CPA_WAIT(2);
        __syncthreads();
        // refill slot (t+3)&3 == (t-1)&3: last read in iter t-1; all threads
        // are past that compute (they reached this barrier). Safe.
        if (t + K1_ST - 1 < K1_NT)
            issue_stage((t + K1_ST - 1) & (K1_ST - 1), t + K1_ST - 1);
        CPA_COMMIT();

        const int slot = t & (K1_ST - 1);
        const uint32_t ab = sb + slot * STG;
        #pragma unroll
        for (int kk = 0; kk < 32; kk += 16) {
            uint32_t a[4][4], bm[2][4];
            #pragma unroll
            for (int mt = 0; mt < 4; mt++)
                LDSM4(a[mt][0], a[mt][1], a[mt][2], a[mt][3], ab + aOff[mt] + kk * 2);
            #pragma unroll
            for (int p = 0; p < 2; p++)
                LDSM4(bm[p][0], bm[p][1], bm[p][2], bm[p][3], ab + bOff[p] + kk * 2);
            #pragma unroll
            for (int mt = 0; mt < 4; mt++) {
                #pragma unroll
                for (int nt = 0; nt < 4; nt++) {
                    const int p = nt >> 1, o = nt & 1;
                    mma16(acc[mt][nt], a[mt], bm[p][o], bm[p][o + 2]);
                }
            }
        }
    }

    // epilogue: bias + sigmoid -> fp32 h_t (output) + bf16 h_t (scratch)
    #pragma unroll
    for (int nt = 0; nt < 4; nt++) {
        const int cn = nBase + wn + nt * 8 + tig * 2;
        const float b0 = U_b[cn]     + W_b[cn];
        const float b1 = U_b[cn + 1] + W_b[cn + 1];
        #pragma unroll
        for (int mt = 0; mt < 4; mt++) {
            const int rm = mBase + wm + mt * 16 + grp;
            const float s00 = sigmoidf_(acc[mt][nt][0] + b0);
            const float s01 = sigmoidf_(acc[mt][nt][1] + b1);
            const float s10 = sigmoidf_(acc[mt][nt][2] + b0);
            const float s11 = sigmoidf_(acc[mt][nt][3] + b1);
            *(float2*)&ht[(size_t)rm * HH + cn]       = make_float2(s00, s01);
            *(float2*)&ht[(size_t)(rm + 8) * HH + cn] = make_float2(s10, s11);
            *(uint32_t*)&g_htb[(size_t)rm * HH + cn]       = packbf2(s00, s01);
            *(uint32_t*)&g_htb[(size_t)(rm + 8) * HH + cn] = packbf2(s10, s11);
        }
    }
}

// ============================================================================
// Kernel 2: pred = log_softmax_seg(h_t @ V_w^T + V_b), fused, all bf16.
// M=16/CTA (grid 512 — more CTAs/SM for latency hiding), 128 threads.
// Warp w handles n8-tiles [nsplit[w], nsplit[w+1]) of 13; all warps share M=16.
// ============================================================================
constexpr int RS2      = 40;
constexpr int K2_A_B   = 16  * RS2 * 2;           // 1280 B
constexpr int K2_B_B   = 104 * RS2 * 2;           // 8320 B
constexpr int K2_STAGE = K2_A_B + K2_B_B;         // 9600
constexpr int K2_SMEM  = 4 * K2_STAGE;            // 38400
constexpr int K2_NT    = HH / 32;                 // 64

__global__ __launch_bounds__(128) void rnn_k2(
    const float* __restrict__ V_b, float* __restrict__ pred)
{
    extern __shared__ char sm2[];
    const uint32_t sb = s2u(sm2);
    const int tid  = threadIdx.x;
    const int warp = tid >> 5, lane = tid & 31;
    const int grp  = lane >> 2, tig = lane & 3;

    const int nsplit[5] = {0, 4, 7, 10, 13};
    const int nbase = nsplit[warp];
    const int ncnt  = nsplit[warp + 1] - nbase;   // 4,3,3,3

    const int mBase = blockIdx.x * 16;
    const __nv_bfloat16* Ap = g_htb + (size_t)mBase * HH;

    float acc[4][4];
    #pragma unroll
    for (int i = 0; i < 4; i++)
        #pragma unroll
        for (int j = 0; j < 4; j++) acc[i][j] = 0.f;

    auto load_stage = [&](int s, int k0) {
        const uint32_t base = sb + s * K2_STAGE;
        if (tid < 64) {                    // A: 16 rows x 4 chunks
            const int row = tid >> 2, cc = (tid & 3) * 8;
            CPA16(base + (uint32_t)(row * RS2 + cc) * 2,
                  Ap + (size_t)row * HH + k0 + cc);
        }
        #pragma unroll
        for (int i = 0; i < 4; i++) {      // B: 104 rows x 4 chunks = 416
            const int c = tid + i * 128;
            if (c < 416) {
                const int row = c >> 2, cc = (c & 3) * 8;
                CPA16(base + K2_A_B + (uint32_t)(row * RS2 + cc) * 2,
                      g_Vwb + (size_t)row * HH + k0 + cc);
            }
        }
    };

    #pragma unroll
    for (int s = 0; s < 3; s++) { load_stage(s, s * 32); CPA_COMMIT(); }

    for (int t = 0; t < K2_NT; t++) {
        CPA_WAIT(2);
        __syncthreads();
        if (t + 3 < K2_NT) load_stage((t + 3) & 3, (t + 3) * 32);
        CPA_COMMIT();

        const int slot = t & 3;
        const __nv_bfloat16* As = (const __nv_bfloat16*)(sm2 + slot * K2_STAGE);
        const __nv_bfloat16* Bs = (const __nv_bfloat16*)(sm2 + slot * K2_STAGE + K2_A_B);
        #pragma unroll
        for (int kk = 0; kk < 32; kk += 16) {
            uint32_t a[4];
            a[0] = *(const uint32_t*)&As[grp * RS2 + kk + 2 * tig];
            a[1] = *(const uint32_t*)&As[(grp + 8) * RS2 + kk + 2 * tig];
            a[2] = *(const uint32_t*)&As[grp * RS2 + kk + 2 * tig + 8];
            a[3] = *(const uint32_t*)&As[(grp + 8) * RS2 + kk + 2 * tig + 8];
            #pragma unroll
            for (int nt = 0; nt < 4; nt++) {
                if (nt < ncnt) {
                    const int c0 = (nbase + nt) * 8 + grp;
                    const uint32_t blo = *(const uint32_t*)&Bs[c0 * RS2 + kk + 2 * tig];
                    const uint32_t bhi = *(const uint32_t*)&Bs[c0 * RS2 + kk + 2 * tig + 8];
                    mma16(acc[nt], a, blo, bhi);
                }
            }
        }
    }

    // -------- fused epilogue: bias + segmented log-softmax ------------------
    __syncthreads();
    float* st   = (float*)sm2;            // [16][108]
    float* segm = st + 16 * 108;
    float* segl = segm + 160;

    #pragma unroll
    for (int nt = 0; nt < 4; nt++) {
        if (nt < ncnt) {
            const int cn = (nbase + nt) * 8 + tig * 2;
            const float b0 = V_b[cn], b1 = V_b[cn + 1];
            st[grp * 108 + cn]           = acc[nt][0] + b0;
            st[grp * 108 + cn + 1]       = acc[nt][1] + b1;
            st[(grp + 8) * 108 + cn]     = acc[nt][2] + b0;
            st[(grp + 8) * 108 + cn + 1] = acc[nt][3] + b1;
        }
    }
    __syncthreads();

    const int bnd[11] = {0, 13, 26, 39, 48, 52, 65, 78, 91, 100, 104};
    if (tid < 16) {
        const float* row = st + tid * 108;
        #pragma unroll
        for (int s = 0; s < 10; s++) {
            float m = -1e30f;
            for (int j = bnd[s]; j < bnd[s + 1]; j++) m = fmaxf(m, row[j]);
            float sum = 0.f;
            for (int j = bnd[s]; j < bnd[s + 1]; j++) sum += expf(row[j] - m);
            segm[tid * 10 + s] = m;
            segl[tid * 10 + s] = logf(sum);
        }
    }
    __syncthreads();

    if (tid < 104) {
        int sg = 0;
        #pragma unroll
        for (int i = 1; i < 10; i++)
            if (tid >= bnd[i]) sg = i;
        #pragma unroll
        for (int r = 0; r < 16; r++)
            pred[(size_t)(mBase + r) * DD + tid] =
                st[r * 108 + tid] - segm[r * 10 + sg] - segl[r * 10 + sg];
    }
}

// ============================================================================
// Launch
// ============================================================================
extern "C" void kernel_launch(void* const* d_in, const int* in_sizes, int n_in,
                              void* d_out, int out_size)
{
    const float* line   = (const float*)d_in[0];
    const float* hidden = (const float*)d_in[1];
    const float* U_w    = (const float*)d_in[2];
    const float* U_b    = (const float*)d_in[3];
    const float* W_w    = (const float*)d_in[4];
    const float* W_b    = (const float*)d_in[5];
    const float* V_w    = (const float*)d_in[6];
    const float* V_b    = (const float*)d_in[7];

    float* out  = (float*)d_out;
    float* pred = out;                          // [8192, 104]
    float* ht   = out + (size_t)BSZ * DD;       // [8192, 2048]

    cudaFuncSetAttribute(rnn_k1, cudaFuncAttributeMaxDynamicSharedMemorySize, K1_SMEM);
    cudaFuncSetAttribute(rnn_k2, cudaFuncAttributeMaxDynamicSharedMemorySize, K2_SMEM);

    const int gcv = (int)((NCVT + 255) / 256);
    cvt_all<<<gcv, 256>>>((const float4*)hidden, (const float4*)U_w,
                          (const float4*)V_w, line, W_w);

    dim3 g1(HH / 128, BSZ / 128);               // (16, 64)
    rnn_k1<<<g1, 256, K1_SMEM>>>(U_b, W_b, ht);
    rnn_k2<<<BSZ / 16, 128, K2_SMEM>>>(V_b, pred);
}

// round 14
// speedup vs baseline: 1.1468x; 1.1468x over previous
#include <cuda_runtime.h>
#include <cuda_bf16.h>
#include <cstdint>

constexpr int BSZ = 8192;
constexpr int HH  = 2048;
constexpr int DD  = 104;
constexpr int DP  = 128;                      // padded D for uniform K loop

// bf16 scratch (device globals — no dynamic allocation)
__device__ __nv_bfloat16 g_hid[(size_t)BSZ * HH];    // 33.5 MB
__device__ __nv_bfloat16 g_Uw [(size_t)HH  * HH];    //  8.4 MB
__device__ __nv_bfloat16 g_line[(size_t)BSZ * DP];   //  2.1 MB (zero-padded)
__device__ __nv_bfloat16 g_Ww [(size_t)HH  * DP];    //  0.5 MB (zero-padded)
__device__ __nv_bfloat16 g_htb[(size_t)BSZ * HH];    // 33.5 MB (h_t in bf16)
__device__ __nv_bfloat16 g_Vwb[(size_t)DD  * HH];    //  0.4 MB

static __device__ __forceinline__ uint32_t s2u(const void* p) {
    uint32_t a;
    asm("{ .reg .u64 t; cvta.to.shared.u64 t, %1; cvt.u32.u64 %0, t; }"
        : "=r"(a) : "l"(p));
    return a;
}

#define LDSM4(r0, r1, r2, r3, addr)                                          \
    asm volatile("ldmatrix.sync.aligned.m8n8.x4.shared.b16 {%0,%1,%2,%3}, [%4];" \
                 : "=r"(r0), "=r"(r1), "=r"(r2), "=r"(r3) : "r"(addr))

static __device__ __forceinline__ void mma16(float c[4], const uint32_t a[4],
                                             uint32_t b0, uint32_t b1) {
    asm volatile(
        "mma.sync.aligned.m16n8k16.row.col.f32.bf16.bf16.f32 "
        "{%0,%1,%2,%3}, {%4,%5,%6,%7}, {%8,%9}, {%0,%1,%2,%3};\n"
        : "+f"(c[0]), "+f"(c[1]), "+f"(c[2]), "+f"(c[3])
        : "r"(a[0]), "r"(a[1]), "r"(a[2]), "r"(a[3]), "r"(b0), "r"(b1));
}

#define CPA16(dst, src) \
    asm volatile("cp.async.cg.shared.global [%0], [%1], 16;" :: "r"(dst), "l"(src) : "memory")
#define CPA_COMMIT() asm volatile("cp.async.commit_group;" ::: "memory")
#define CPA_WAIT(n)  asm volatile("cp.async.wait_group %0;" :: "n"(n) : "memory")

static __device__ __forceinline__ float sigmoidf_(float x) {
    return 1.0f / (1.0f + __expf(-x));
}
static __device__ __forceinline__ uint32_t packbf2(float x, float y) {
    __nv_bfloat162 h = __floats2bfloat162_rn(x, y);
    return *(uint32_t*)&h;
}
// SW64 swizzle applied to a FULL byte offset (row*64 + col, col < 64):
// XOR bits [4:5] with row bits [1:2]. Safe only on the complete sum.
static __device__ __forceinline__ uint32_t swz64(uint32_t b) {
    return b ^ ((b >> 3) & 0x30u);
}

// ============================================================================
// Single fused convert kernel (measured 25us)
// ============================================================================
constexpr size_t NH4   = (size_t)BSZ * HH / 4;       // 4194304
constexpr size_t NU4   = (size_t)HH  * HH / 4;       // 1048576
constexpr size_t NV4   = (size_t)DD  * HH / 4;       // 53248
constexpr size_t NF4   = NH4 + NU4 + NV4;
constexpr size_t NPAD  = (size_t)(BSZ + HH) * DP;
constexpr size_t NCVT  = NF4 + NPAD;

__global__ __launch_bounds__(256) void cvt_all(
    const float4* __restrict__ hid, const float4* __restrict__ uw,
    const float4* __restrict__ vw,  const float*  __restrict__ line,
    const float*  __restrict__ ww)
{
    size_t i = (size_t)blockIdx.x * blockDim.x + threadIdx.x;
    if (i >= NCVT) return;
    if (i < NF4) {
        float4 v; __nv_bfloat16* dst;
        if (i < NH4)            { v = hid[i];              dst = g_hid + i * 4; }
        else if (i < NH4 + NU4) { v = uw[i - NH4];         dst = g_Uw  + (i - NH4) * 4; }
        else                    { v = vw[i - NH4 - NU4];   dst = g_Vwb + (i - NH4 - NU4) * 4; }
        uint2 o;
        o.x = packbf2(v.x, v.y);
        o.y = packbf2(v.z, v.w);
        *(uint2*)dst = o;
    } else {
        size_t j   = i - NF4;
        size_t row = j >> 7;
        int    col = (int)(j & 127);
        float v = 0.f;
        if (col < DD)
            v = (row < BSZ) ? line[row * DD + col] : ww[(row - BSZ) * DD + col];
        ((row < BSZ) ? g_line : g_Ww)[((row < BSZ) ? row : row - BSZ) * DP + col] =
            __float2bfloat16(v);
    }
}

// ============================================================================
// Kernel 1 — R5 structure (CTA 128x128, BK=32, 256 thr, 2x4 warps, 64x32
// tiles, 4-stage cp.async, WAIT(2), 1 barrier/iter) with SW64-swizzled smem.
// FIX vs R13: fragment addresses precomputed per kk-half as
//   rb + ((lh*16 + h*32) ^ m),  m = (rb>>3)&0x30
// — no runtime add into swizzled bits, no carry into row bits.
// ============================================================================
constexpr int OP1     = 128 * 64;             // 8192 B per operand per stage
constexpr int STG1    = 2 * OP1;              // 16384 B per stage
constexpr int K1_ST   = 4;
constexpr int K1_SMEM = K1_ST * STG1;         // 65536 (2 CTAs = 128KB)
constexpr int K1_NT1  = HH / 32;              // 64
constexpr int K1_NT   = K1_NT1 + DP / 32;     // 68

__global__ __launch_bounds__(256) void rnn_k1(
    const float* __restrict__ U_b, const float* __restrict__ W_b,
    float* __restrict__ ht)
{
    extern __shared__ char sm1[];
    const uint32_t sb = s2u(sm1);

    const int tid  = threadIdx.x;
    const int warp = tid >> 5, lane = tid & 31;
    const int wm   = (warp >> 2) * 64;
    const int wn   = (warp & 3) * 32;
    const int grp  = lane >> 2, tig = lane & 3;
    const int lr16 = lane & 15, lh = lane >> 4;

    const int mBase = blockIdx.y * 128;
    const int nBase = blockIdx.x * 128;

    // Fragment offsets, one per kk-half (h=0: bytes lh*16, h=1: +32).
    uint32_t aOff[4][2], bOff[2][2];
    #pragma unroll
    for (int mt = 0; mt < 4; mt++) {
        const uint32_t rb = (uint32_t)(wm + mt * 16 + lr16) * 64;
        const uint32_t m  = (rb >> 3) & 0x30u;
        aOff[mt][0] = rb + (((uint32_t)lh * 16)      ^ m);
        aOff[mt][1] = rb + (((uint32_t)lh * 16 + 32) ^ m);
    }
    #pragma unroll
    for (int p = 0; p < 2; p++) {
        const uint32_t rb = (uint32_t)(wn + p * 16 + lr16) * 64;
        const uint32_t m  = (rb >> 3) & 0x30u;
        bOff[p][0] = OP1 + rb + (((uint32_t)lh * 16)      ^ m);
        bOff[p][1] = OP1 + rb + (((uint32_t)lh * 16 + 32) ^ m);
    }

    // producer (R5 mapping — coalescing-optimal): row tid>>1, 32B half tid&1.
    // swz64 on the complete offset — correct.
    const int lrow = tid >> 1;
    const int lcb  = (tid & 1) * 16;              // bf16 elems
    const __nv_bfloat16* hA = g_hid  + (size_t)(mBase + lrow) * HH + lcb;
    const __nv_bfloat16* uB = g_Uw   + (size_t)(nBase + lrow) * HH + lcb;
    const __nv_bfloat16* lA = g_line + (size_t)(mBase + lrow) * DP + lcb;
    const __nv_bfloat16* wB = g_Ww   + (size_t)(nBase + lrow) * DP + lcb;
    const uint32_t b0   = (uint32_t)lrow * 64 + (uint32_t)lcb * 2;
    const uint32_t dOf0 = swz64(b0);
    const uint32_t dOf1 = swz64(b0 + 16);

    auto issue_stage = [&](int slot, int f) {
        const uint32_t s0 = sb + slot * STG1;
        const __nv_bfloat16 *sA, *sB;
        if (f < K1_NT1) { sA = hA + f * 32;             sB = uB + f * 32; }
        else            { sA = lA + (f - K1_NT1) * 32;  sB = wB + (f - K1_NT1) * 32; }
        CPA16(s0 + dOf0,       sA);
        CPA16(s0 + dOf1,       sA + 8);
        CPA16(s0 + OP1 + dOf0, sB);
        CPA16(s0 + OP1 + dOf1, sB + 8);
    };

    float acc[4][4][4];
    #pragma unroll
    for (int i = 0; i < 4; i++)
        #pragma unroll
        for (int j = 0; j < 4; j++)
            #pragma unroll
            for (int k = 0; k < 4; k++) acc[i][j][k] = 0.f;

    #pragma unroll
    for (int s = 0; s < K1_ST - 1; s++) { issue_stage(s, s); CPA_COMMIT(); }

    for (int t = 0; t < K1_NT; t++) {
        CPA_WAIT(2);
        __syncthreads();
        // refill slot (t+3)&3 == (t-1)&3: last read in iter t-1; all threads
        // are past that compute (they reached this barrier). Safe.
        if (t + K1_ST - 1 < K1_NT)
            issue_stage((t + K1_ST - 1) & (K1_ST - 1), t + K1_ST - 1);
        CPA_COMMIT();

        const int slot = t & (K1_ST - 1);
        const uint32_t stg = sb + slot * STG1;
        #pragma unroll
        for (int h = 0; h < 2; h++) {
            uint32_t a[4][4], bm[2][4];
            #pragma unroll
            for (int mt = 0; mt < 4; mt++)
                LDSM4(a[mt][0], a[mt][1], a[mt][2], a[mt][3], stg + aOff[mt][h]);
            #pragma unroll
            for (int p = 0; p < 2; p++)
                LDSM4(bm[p][0], bm[p][1], bm[p][2], bm[p][3], stg + bOff[p][h]);
            #pragma unroll
            for (int mt = 0; mt < 4; mt++) {
                #pragma unroll
                for (int nt = 0; nt < 4; nt++) {
                    const int p = nt >> 1, o = nt & 1;
                    mma16(acc[mt][nt], a[mt], bm[p][o], bm[p][o + 2]);
                }
            }
        }
    }

    // epilogue: bias + sigmoid -> fp32 h_t (output) + bf16 h_t (scratch)
    #pragma unroll
    for (int nt = 0; nt < 4; nt++) {
        const int cn = nBase + wn + nt * 8 + tig * 2;
        const float b0f = U_b[cn]     + W_b[cn];
        const float b1f = U_b[cn + 1] + W_b[cn + 1];
        #pragma unroll
        for (int mt = 0; mt < 4; mt++) {
            const int rm = mBase + wm + mt * 16 + grp;
            const float s00 = sigmoidf_(acc[mt][nt][0] + b0f);
            const float s01 = sigmoidf_(acc[mt][nt][1] + b1f);
            const float s10 = sigmoidf_(acc[mt][nt][2] + b0f);
            const float s11 = sigmoidf_(acc[mt][nt][3] + b1f);
            *(float2*)&ht[(size_t)rm * HH + cn]       = make_float2(s00, s01);
            *(float2*)&ht[(size_t)(rm + 8) * HH + cn] = make_float2(s10, s11);
            *(uint32_t*)&g_htb[(size_t)rm * HH + cn]       = packbf2(s00, s01);
            *(uint32_t*)&g_htb[(size_t)(rm + 8) * HH + cn] = packbf2(s10, s11);
        }
    }
}

// ============================================================================
// Kernel 2 — EXACT R5 config (measured-good): M=32/CTA, grid 256, 128 thr,
// BK=32 bf16, 4-stage cp.async, fused bias + segmented log-softmax.
// ============================================================================
constexpr int RS2      = 40;
constexpr int K2_A_B   = 32  * RS2 * 2;           // 2560 B
constexpr int K2_B_B   = 104 * RS2 * 2;           // 8320 B
constexpr int K2_STAGE = K2_A_B + K2_B_B;         // 10880
constexpr int K2_SMEM  = 4 * K2_STAGE;            // 43520
constexpr int K2_NT    = HH / 32;                 // 64

__global__ __launch_bounds__(128) void rnn_k2(
    const float* __restrict__ V_b, float* __restrict__ pred)
{
    extern __shared__ char sm2[];
    const uint32_t sb = s2u(sm2);
    const int tid  = threadIdx.x;
    const int warp = tid >> 5, lane = tid & 31;
    const int wm   = (warp & 1) * 16;
    const int nh   = warp >> 1;
    const int ntn  = 7 - nh;                 // 7 or 6 n8-tiles
    const int grp  = lane >> 2, tig = lane & 3;

    const int mBase = blockIdx.x * 32;
    const __nv_bfloat16* Ap = g_htb + (size_t)mBase * HH;

    float acc[7][4];
    #pragma unroll
    for (int i = 0; i < 7; i++)
        #pragma unroll
        for (int j = 0; j < 4; j++) acc[i][j] = 0.f;

    auto load_stage = [&](int s, int k0) {
        const uint32_t base = sb + s * K2_STAGE;
        {
            const int row = tid >> 2, cc = (tid & 3) * 8;
            CPA16(base + (uint32_t)(row * RS2 + cc) * 2,
                  Ap + (size_t)row * HH + k0 + cc);
        }
        #pragma unroll
        for (int i = 0; i < 4; i++) {
            const int c = tid + i * 128;
            if (c < 416) {
                const int row = c >> 2, cc = (c & 3) * 8;
                CPA16(base + K2_A_B + (uint32_t)(row * RS2 + cc) * 2,
                      g_Vwb + (size_t)row * HH + k0 + cc);
            }
        }
    };

    #pragma unroll
    for (int s = 0; s < 3; s++) { load_stage(s, s * 32); CPA_COMMIT(); }

    for (int t = 0; t < K2_NT; t++) {
        CPA_WAIT(2);
        __syncthreads();
        if (t + 3 < K2_NT) load_stage((t + 3) & 3, (t + 3) * 32);
        CPA_COMMIT();

        const int slot = t & 3;
        const __nv_bfloat16* As = (const __nv_bfloat16*)(sm2 + slot * K2_STAGE);
        const __nv_bfloat16* Bs = (const __nv_bfloat16*)(sm2 + slot * K2_STAGE + K2_A_B);
        #pragma unroll
        for (int kk = 0; kk < 32; kk += 16) {
            uint32_t a[4];
            const int r0 = wm + grp;
            a[0] = *(const uint32_t*)&As[r0 * RS2 + kk + 2 * tig];
            a[1] = *(const uint32_t*)&As[(r0 + 8) * RS2 + kk + 2 * tig];
            a[2] = *(const uint32_t*)&As[r0 * RS2 + kk + 2 * tig + 8];
            a[3] = *(const uint32_t*)&As[(r0 + 8) * RS2 + kk + 2 * tig + 8];
            #pragma unroll
            for (int nt = 0; nt < 7; nt++) {
                if (nt < ntn) {
                    const int c0 = (nh * 7 + nt) * 8 + grp;
                    const uint32_t blo = *(const uint32_t*)&Bs[c0 * RS2 + kk + 2 * tig];
                    const uint32_t bhi = *(const uint32_t*)&Bs[c0 * RS2 + kk + 2 * tig + 8];
                    mma16(acc[nt], a, blo, bhi);
                }
            }
        }
    }

    // -------- fused epilogue: bias + segmented log-softmax ------------------
    __syncthreads();
    float* st   = (float*)sm2;            // [32][108]
    float* segm = st + 32 * 108;
    float* segl = segm + 320;

    #pragma unroll
    for (int nt = 0; nt < 7; nt++) {
        if (nt < ntn) {
            const int cn = (nh * 7 + nt) * 8 + tig * 2;
            const float b0 = V_b[cn], b1 = V_b[cn + 1];
            const int r = wm + grp;
            st[r * 108 + cn]           = acc[nt][0] + b0;
            st[r * 108 + cn + 1]       = acc[nt][1] + b1;
            st[(r + 8) * 108 + cn]     = acc[nt][2] + b0;
            st[(r + 8) * 108 + cn + 1] = acc[nt][3] + b1;
        }
    }
    __syncthreads();

    const int bnd[11] = {0, 13, 26, 39, 48, 52, 65, 78, 91, 100, 104};
    if (tid < 32) {
        const float* row = st + tid * 108;
        #pragma unroll
        for (int s = 0; s < 10; s++) {
            float m = -1e30f;
            for (int j = bnd[s]; j < bnd[s + 1]; j++) m = fmaxf(m, row[j]);
            float sum = 0.f;
            for (int j = bnd[s]; j < bnd[s + 1]; j++) sum += expf(row[j] - m);
            segm[tid * 10 + s] = m;
            segl[tid * 10 + s] = logf(sum);
        }
    }
    __syncthreads();

    if (tid < 104) {
        int sg = 0;
        #pragma unroll
        for (int i = 1; i < 10; i++)
            if (tid >= bnd[i]) sg = i;
        for (int r = 0; r < 32; r++)
            pred[(size_t)(mBase + r) * DD + tid] =
                st[r * 108 + tid] - segm[r * 10 + sg] - segl[r * 10 + sg];
    }
}

// ============================================================================
// Launch
// ============================================================================
extern "C" void kernel_launch(void* const* d_in, const int* in_sizes, int n_in,
                              void* d_out, int out_size)
{
    const float* line   = (const float*)d_in[0];
    const float* hidden = (const float*)d_in[1];
    const float* U_w    = (const float*)d_in[2];
    const float* U_b    = (const float*)d_in[3];
    const float* W_w    = (const float*)d_in[4];
    const float* W_b    = (const float*)d_in[5];
    const float* V_w    = (const float*)d_in[6];
    const float* V_b    = (const float*)d_in[7];

    float* out  = (float*)d_out;
    float* pred = out;                          // [8192, 104]
    float* ht   = out + (size_t)BSZ * DD;       // [8192, 2048]

    cudaFuncSetAttribute(rnn_k1, cudaFuncAttributeMaxDynamicSharedMemorySize, K1_SMEM);
    cudaFuncSetAttribute(rnn_k2, cudaFuncAttributeMaxDynamicSharedMemorySize, K2_SMEM);

    const int gcv = (int)((NCVT + 255) / 256);
    cvt_all<<<gcv, 256>>>((const float4*)hidden, (const float4*)U_w,
                          (const float4*)V_w, line, W_w);

    dim3 g1(HH / 128, BSZ / 128);               // (16, 64)
    rnn_k1<<<g1, 256, K1_SMEM>>>(U_b, W_b, ht);
    rnn_k2<<<BSZ / 32, 128, K2_SMEM>>>(V_b, pred);
}

// round 15
// speedup vs baseline: 1.1512x; 1.0038x over previous
#include <cuda_runtime.h>
#include <cuda_bf16.h>
#include <cstdint>

constexpr int BSZ = 8192;
constexpr int HH  = 2048;
constexpr int DD  = 104;
constexpr int DP  = 128;                      // padded D for uniform K loop

// bf16 scratch (device globals — no dynamic allocation)
__device__ __nv_bfloat16 g_hid[(size_t)BSZ * HH];    // 33.5 MB
__device__ __nv_bfloat16 g_Uw [(size_t)HH  * HH];    //  8.4 MB
__device__ __nv_bfloat16 g_line[(size_t)BSZ * DP];   //  2.1 MB (zero-padded)
__device__ __nv_bfloat16 g_Ww [(size_t)HH  * DP];    //  0.5 MB (zero-padded)
__device__ __nv_bfloat16 g_htb[(size_t)BSZ * HH];    // 33.5 MB (h_t in bf16)
__device__ __nv_bfloat16 g_Vwb[(size_t)DD  * HH];    //  0.4 MB

static __device__ __forceinline__ uint32_t s2u(const void* p) {
    uint32_t a;
    asm("{ .reg .u64 t; cvta.to.shared.u64 t, %1; cvt.u32.u64 %0, t; }"
        : "=r"(a) : "l"(p));
    return a;
}

#define LDSM4(r0, r1, r2, r3, addr)                                          \
    asm volatile("ldmatrix.sync.aligned.m8n8.x4.shared.b16 {%0,%1,%2,%3}, [%4];" \
                 : "=r"(r0), "=r"(r1), "=r"(r2), "=r"(r3) : "r"(addr))

static __device__ __forceinline__ void mma16(float c[4], const uint32_t a[4],
                                             uint32_t b0, uint32_t b1) {
    asm volatile(
        "mma.sync.aligned.m16n8k16.row.col.f32.bf16.bf16.f32 "
        "{%0,%1,%2,%3}, {%4,%5,%6,%7}, {%8,%9}, {%0,%1,%2,%3};\n"
        : "+f"(c[0]), "+f"(c[1]), "+f"(c[2]), "+f"(c[3])
        : "r"(a[0]), "r"(a[1]), "r"(a[2]), "r"(a[3]), "r"(b0), "r"(b1));
}

#define CPA16(dst, src) \
    asm volatile("cp.async.cg.shared.global [%0], [%1], 16;" :: "r"(dst), "l"(src) : "memory")
#define CPA_COMMIT() asm volatile("cp.async.commit_group;" ::: "memory")
#define CPA_WAIT(n)  asm volatile("cp.async.wait_group %0;" :: "n"(n) : "memory")

static __device__ __forceinline__ float sigmoidf_(float x) {
    return 1.0f / (1.0f + __expf(-x));
}
static __device__ __forceinline__ uint32_t packbf2(float x, float y) {
    __nv_bfloat162 h = __floats2bfloat162_rn(x, y);
    return *(uint32_t*)&h;
}
// SW64 swizzle applied to a FULL byte offset (row*64 + col, col < 64).
static __device__ __forceinline__ uint32_t swz64(uint32_t b) {
    return b ^ ((b >> 3) & 0x30u);
}

// ============================================================================
// Single fused convert kernel (measured 25us)
// ============================================================================
constexpr size_t NH4   = (size_t)BSZ * HH / 4;       // 4194304
constexpr size_t NU4   = (size_t)HH  * HH / 4;       // 1048576
constexpr size_t NV4   = (size_t)DD  * HH / 4;       // 53248
constexpr size_t NF4   = NH4 + NU4 + NV4;
constexpr size_t NPAD  = (size_t)(BSZ + HH) * DP;
constexpr size_t NCVT  = NF4 + NPAD;

__global__ __launch_bounds__(256) void cvt_all(
    const float4* __restrict__ hid, const float4* __restrict__ uw,
    const float4* __restrict__ vw,  const float*  __restrict__ line,
    const float*  __restrict__ ww)
{
    size_t i = (size_t)blockIdx.x * blockDim.x + threadIdx.x;
    if (i >= NCVT) return;
    if (i < NF4) {
        float4 v; __nv_bfloat16* dst;
        if (i < NH4)            { v = hid[i];              dst = g_hid + i * 4; }
        else if (i < NH4 + NU4) { v = uw[i - NH4];         dst = g_Uw  + (i - NH4) * 4; }
        else                    { v = vw[i - NH4 - NU4];   dst = g_Vwb + (i - NH4 - NU4) * 4; }
        uint2 o;
        o.x = packbf2(v.x, v.y);
        o.y = packbf2(v.z, v.w);
        *(uint2*)dst = o;
    } else {
        size_t j   = i - NF4;
        size_t row = j >> 7;
        int    col = (int)(j & 127);
        float v = 0.f;
        if (col < DD)
            v = (row < BSZ) ? line[row * DD + col] : ww[(row - BSZ) * DD + col];
        ((row < BSZ) ? g_line : g_Ww)[((row < BSZ) ? row : row - BSZ) * DP + col] =
            __float2bfloat16(v);
    }
}

// ============================================================================
// Kernel 1 — UNCHANGED from Round-14 winner (measured ~317us):
// CTA 128x128, BK=32, 256 thr, 2x4 warps, 64x32 tiles, SW64-swizzled smem,
// 4-stage cp.async, WAIT(2), 1 barrier/iter.
// ============================================================================
constexpr int OP1     = 128 * 64;             // 8192 B per operand per stage
constexpr int STG1    = 2 * OP1;              // 16384 B per stage
constexpr int K1_ST   = 4;
constexpr int K1_SMEM = K1_ST * STG1;         // 65536 (2 CTAs = 128KB)
constexpr int K1_NT1  = HH / 32;              // 64
constexpr int K1_NT   = K1_NT1 + DP / 32;     // 68

__global__ __launch_bounds__(256) void rnn_k1(
    const float* __restrict__ U_b, const float* __restrict__ W_b,
    float* __restrict__ ht)
{
    extern __shared__ char sm1[];
    const uint32_t sb = s2u(sm1);

    const int tid  = threadIdx.x;
    const int warp = tid >> 5, lane = tid & 31;
    const int wm   = (warp >> 2) * 64;
    const int wn   = (warp & 3) * 32;
    const int grp  = lane >> 2, tig = lane & 3;
    const int lr16 = lane & 15, lh = lane >> 4;

    const int mBase = blockIdx.y * 128;
    const int nBase = blockIdx.x * 128;

    // Fragment offsets, one per kk-half (h=0: bytes lh*16, h=1: +32).
    uint32_t aOff[4][2], bOff[2][2];
    #pragma unroll
    for (int mt = 0; mt < 4; mt++) {
        const uint32_t rb = (uint32_t)(wm + mt * 16 + lr16) * 64;
        const uint32_t m  = (rb >> 3) & 0x30u;
        aOff[mt][0] = rb + (((uint32_t)lh * 16)      ^ m);
        aOff[mt][1] = rb + (((uint32_t)lh * 16 + 32) ^ m);
    }
    #pragma unroll
    for (int p = 0; p < 2; p++) {
        const uint32_t rb = (uint32_t)(wn + p * 16 + lr16) * 64;
        const uint32_t m  = (rb >> 3) & 0x30u;
        bOff[p][0] = OP1 + rb + (((uint32_t)lh * 16)      ^ m);
        bOff[p][1] = OP1 + rb + (((uint32_t)lh * 16 + 32) ^ m);
    }

    // producer (coalescing-optimal): row tid>>1, 32B half tid&1.
    const int lrow = tid >> 1;
    const int lcb  = (tid & 1) * 16;              // bf16 elems
    const __nv_bfloat16* hA = g_hid  + (size_t)(mBase + lrow) * HH + lcb;
    const __nv_bfloat16* uB = g_Uw   + (size_t)(nBase + lrow) * HH + lcb;
    const __nv_bfloat16* lA = g_line + (size_t)(mBase + lrow) * DP + lcb;
    const __nv_bfloat16* wB = g_Ww   + (size_t)(nBase + lrow) * DP + lcb;
    const uint32_t b0   = (uint32_t)lrow * 64 + (uint32_t)lcb * 2;
    const uint32_t dOf0 = swz64(b0);
    const uint32_t dOf1 = swz64(b0 + 16);

    auto issue_stage = [&](int slot, int f) {
        const uint32_t s0 = sb + slot * STG1;
        const __nv_bfloat16 *sA, *sB;
        if (f < K1_NT1) { sA = hA + f * 32;             sB = uB + f * 32; }
        else            { sA = lA + (f - K1_NT1) * 32;  sB = wB + (f - K1_NT1) * 32; }
        CPA16(s0 + dOf0,       sA);
        CPA16(s0 + dOf1,       sA + 8);
        CPA16(s0 + OP1 + dOf0, sB);
        CPA16(s0 + OP1 + dOf1, sB + 8);
    };

    float acc[4][4][4];
    #pragma unroll
    for (int i = 0; i < 4; i++)
        #pragma unroll
        for (int j = 0; j < 4; j++)
            #pragma unroll
            for (int k = 0; k < 4; k++) acc[i][j][k] = 0.f;

    #pragma unroll
    for (int s = 0; s < K1_ST - 1; s++) { issue_stage(s, s); CPA_COMMIT(); }

    for (int t = 0; t < K1_NT; t++) {
        CPA_WAIT(2);
        __syncthreads();
        if (t + K1_ST - 1 < K1_NT)
            issue_stage((t + K1_ST - 1) & (K1_ST - 1), t + K1_ST - 1);
        CPA_COMMIT();

        const int slot = t & (K1_ST - 1);
        const uint32_t stg = sb + slot * STG1;
        #pragma unroll
        for (int h = 0; h < 2; h++) {
            uint32_t a[4][4], bm[2][4];
            #pragma unroll
            for (int mt = 0; mt < 4; mt++)
                LDSM4(a[mt][0], a[mt][1], a[mt][2], a[mt][3], stg + aOff[mt][h]);
            #pragma unroll
            for (int p = 0; p < 2; p++)
                LDSM4(bm[p][0], bm[p][1], bm[p][2], bm[p][3], stg + bOff[p][h]);
            #pragma unroll
            for (int mt = 0; mt < 4; mt++) {
                #pragma unroll
                for (int nt = 0; nt < 4; nt++) {
                    const int p = nt >> 1, o = nt & 1;
                    mma16(acc[mt][nt], a[mt], bm[p][o], bm[p][o + 2]);
                }
            }
        }
    }

    // epilogue: bias + sigmoid -> fp32 h_t (output) + bf16 h_t (scratch)
    #pragma unroll
    for (int nt = 0; nt < 4; nt++) {
        const int cn = nBase + wn + nt * 8 + tig * 2;
        const float b0f = U_b[cn]     + W_b[cn];
        const float b1f = U_b[cn + 1] + W_b[cn + 1];
        #pragma unroll
        for (int mt = 0; mt < 4; mt++) {
            const int rm = mBase + wm + mt * 16 + grp;
            const float s00 = sigmoidf_(acc[mt][nt][0] + b0f);
            const float s01 = sigmoidf_(acc[mt][nt][1] + b1f);
            const float s10 = sigmoidf_(acc[mt][nt][2] + b0f);
            const float s11 = sigmoidf_(acc[mt][nt][3] + b1f);
            *(float2*)&ht[(size_t)rm * HH + cn]       = make_float2(s00, s01);
            *(float2*)&ht[(size_t)(rm + 8) * HH + cn] = make_float2(s10, s11);
            *(uint32_t*)&g_htb[(size_t)rm * HH + cn]       = packbf2(s00, s01);
            *(uint32_t*)&g_htb[(size_t)(rm + 8) * HH + cn] = packbf2(s10, s11);
        }
    }
}

// ============================================================================
// Kernel 2: pred = log_softmax_seg(h_t @ V_w^T + V_b), fused, all bf16.
// M=32/CTA (grid 256), NOW 256 threads = 8 warps: (warp&1)->M half,
// (warp>>1)->N group of {4,3,3,3} n8-tiles. 6-stage cp.async, WAIT(4).
// 2 warps/SMSP hides LDS latency; per-warp acc <= 16 regs.
// ============================================================================
constexpr int RS2      = 40;
constexpr int K2_A_B   = 32  * RS2 * 2;           // 2560 B
constexpr int K2_B_B   = 104 * RS2 * 2;           // 8320 B
constexpr int K2_STAGE = K2_A_B + K2_B_B;         // 10880
constexpr int K2_ST    = 6;
constexpr int K2_SMEM  = K2_ST * K2_STAGE;        // 65280
constexpr int K2_NT    = HH / 32;                 // 64

__global__ __launch_bounds__(256) void rnn_k2(
    const float* __restrict__ V_b, float* __restrict__ pred)
{
    extern __shared__ char sm2[];
    const uint32_t sb = s2u(sm2);
    const int tid  = threadIdx.x;
    const int warp = tid >> 5, lane = tid & 31;
    const int wm   = (warp & 1) * 16;        // M half: 0 / 16
    const int ng   = warp >> 1;              // N group 0..3
    const int grp  = lane >> 2, tig = lane & 3;

    const int nsplit[5] = {0, 4, 7, 10, 13};
    const int nbase = nsplit[ng];
    const int ncnt  = nsplit[ng + 1] - nbase;     // 4,3,3,3

    const int mBase = blockIdx.x * 32;
    const __nv_bfloat16* Ap = g_htb + (size_t)mBase * HH;

    float acc[4][4];
    #pragma unroll
    for (int i = 0; i < 4; i++)
        #pragma unroll
        for (int j = 0; j < 4; j++) acc[i][j] = 0.f;

    auto load_stage = [&](int s, int k0) {
        const uint32_t base = sb + s * K2_STAGE;
        if (tid < 128) {                   // A: 32 rows x 4 chunks = 128
            const int row = tid >> 2, cc = (tid & 3) * 8;
            CPA16(base + (uint32_t)(row * RS2 + cc) * 2,
                  Ap + (size_t)row * HH + k0 + cc);
        }
        #pragma unroll
        for (int i = 0; i < 2; i++) {      // B: 104 rows x 4 chunks = 416
            const int c = tid + i * 256;
            if (c < 416) {
                const int row = c >> 2, cc = (c & 3) * 8;
                CPA16(base + K2_A_B + (uint32_t)(row * RS2 + cc) * 2,
                      g_Vwb + (size_t)row * HH + k0 + cc);
            }
        }
    };

    #pragma unroll
    for (int s = 0; s < K2_ST - 1; s++) { load_stage(s, s * 32); CPA_COMMIT(); }

    int slot = 0;
    for (int t = 0; t < K2_NT; t++) {
        CPA_WAIT(4);
        __syncthreads();
        // refill slot (slot+5)%6 == previous iteration's slot: safe (all
        // threads passed that compute to reach this barrier).
        if (t + K2_ST - 1 < K2_NT) {
            int rs = slot + K2_ST - 1; if (rs >= K2_ST) rs -= K2_ST;
            load_stage(rs, (t + K2_ST - 1) * 32);
        }
        CPA_COMMIT();   // commit every iter (possibly empty) for uniform group math

        const __nv_bfloat16* As = (const __nv_bfloat16*)(sm2 + slot * K2_STAGE);
        const __nv_bfloat16* Bs = (const __nv_bfloat16*)(sm2 + slot * K2_STAGE + K2_A_B);
        #pragma unroll
        for (int kk = 0; kk < 32; kk += 16) {
            uint32_t a[4];
            const int r0 = wm + grp;
            a[0] = *(const uint32_t*)&As[r0 * RS2 + kk + 2 * tig];
            a[1] = *(const uint32_t*)&As[(r0 + 8) * RS2 + kk + 2 * tig];
            a[2] = *(const uint32_t*)&As[r0 * RS2 + kk + 2 * tig + 8];
            a[3] = *(const uint32_t*)&As[(r0 + 8) * RS2 + kk + 2 * tig + 8];
            #pragma unroll
            for (int nt = 0; nt < 4; nt++) {
                if (nt < ncnt) {
                    const int c0 = (nbase + nt) * 8 + grp;
                    const uint32_t blo = *(const uint32_t*)&Bs[c0 * RS2 + kk + 2 * tig];
                    const uint32_t bhi = *(const uint32_t*)&Bs[c0 * RS2 + kk + 2 * tig + 8];
                    mma16(acc[nt], a, blo, bhi);
                }
            }
        }
        if (++slot == K2_ST) slot = 0;
    }

    // -------- fused epilogue: bias + segmented log-softmax ------------------
    __syncthreads();
    float* st   = (float*)sm2;            // [32][108]
    float* segm = st + 32 * 108;
    float* segl = segm + 320;

    #pragma unroll
    for (int nt = 0; nt < 4; nt++) {
        if (nt < ncnt) {
            const int cn = (nbase + nt) * 8 + tig * 2;
            const float b0 = V_b[cn], b1 = V_b[cn + 1];
            const int r = wm + grp;
            st[r * 108 + cn]           = acc[nt][0] + b0;
            st[r * 108 + cn + 1]       = acc[nt][1] + b1;
            st[(r + 8) * 108 + cn]     = acc[nt][2] + b0;
            st[(r + 8) * 108 + cn + 1] = acc[nt][3] + b1;
        }
    }
    __syncthreads();

    const int bnd[11] = {0, 13, 26, 39, 48, 52, 65, 78, 91, 100, 104};
    if (tid < 32) {
        const float* row = st + tid * 108;
        #pragma unroll
        for (int s = 0; s < 10; s++) {
            float m = -1e30f;
            for (int j = bnd[s]; j < bnd[s + 1]; j++) m = fmaxf(m, row[j]);
            float sum = 0.f;
            for (int j = bnd[s]; j < bnd[s + 1]; j++) sum += expf(row[j] - m);
            segm[tid * 10 + s] = m;
            segl[tid * 10 + s] = logf(sum);
        }
    }
    __syncthreads();

    if (tid < 104) {
        int sg = 0;
        #pragma unroll
        for (int i = 1; i < 10; i++)
            if (tid >= bnd[i]) sg = i;
        for (int r = 0; r < 32; r++)
            pred[(size_t)(mBase + r) * DD + tid] =
                st[r * 108 + tid] - segm[r * 10 + sg] - segl[r * 10 + sg];
    }
}

// ============================================================================
// Launch
// ============================================================================
extern "C" void kernel_launch(void* const* d_in, const int* in_sizes, int n_in,
                              void* d_out, int out_size)
{
    const float* line   = (const float*)d_in[0];
    const float* hidden = (const float*)d_in[1];
    const float* U_w    = (const float*)d_in[2];
    const float* U_b    = (const float*)d_in[3];
    const float* W_w    = (const float*)d_in[4];
    const float* W_b    = (const float*)d_in[5];
    const float* V_w    = (const float*)d_in[6];
    const float* V_b    = (const float*)d_in[7];

    float* out  = (float*)d_out;
    float* pred = out;                          // [8192, 104]
    float* ht   = out + (size_t)BSZ * DD;       // [8192, 2048]

    cudaFuncSetAttribute(rnn_k1, cudaFuncAttributeMaxDynamicSharedMemorySize, K1_SMEM);
    cudaFuncSetAttribute(rnn_k2, cudaFuncAttributeMaxDynamicSharedMemorySize, K2_SMEM);

    const int gcv = (int)((NCVT + 255) / 256);
    cvt_all<<<gcv, 256>>>((const float4*)hidden, (const float4*)U_w,
                          (const float4*)V_w, line, W_w);

    dim3 g1(HH / 128, BSZ / 128);               // (16, 64)
    rnn_k1<<<g1, 256, K1_SMEM>>>(U_b, W_b, ht);
    rnn_k2<<<BSZ / 32, 256, K2_SMEM>>>(V_b, pred);
}

// round 16
// speedup vs baseline: 1.2233x; 1.0626x over previous
#include <cuda_runtime.h>
#include <cuda_bf16.h>
#include <cstdint>

constexpr int BSZ = 8192;
constexpr int HH  = 2048;
constexpr int DD  = 104;
constexpr int DP  = 128;                      // padded D for uniform K loop

// bf16 scratch (device globals — no dynamic allocation)
__device__ __nv_bfloat16 g_hid[(size_t)BSZ * HH];    // 33.5 MB
__device__ __nv_bfloat16 g_Uw [(size_t)HH  * HH];    //  8.4 MB
__device__ __nv_bfloat16 g_line[(size_t)BSZ * DP];   //  2.1 MB (zero-padded)
__device__ __nv_bfloat16 g_Ww [(size_t)HH  * DP];    //  0.5 MB (zero-padded)
__device__ __nv_bfloat16 g_htb[(size_t)BSZ * HH];    // 33.5 MB (h_t in bf16)
__device__ __nv_bfloat16 g_Vwb[(size_t)DD  * HH];    //  0.4 MB

static __device__ __forceinline__ uint32_t s2u(const void* p) {
    uint32_t a;
    asm("{ .reg .u64 t; cvta.to.shared.u64 t, %1; cvt.u32.u64 %0, t; }"
        : "=r"(a) : "l"(p));
    return a;
}

#define LDSM4(r0, r1, r2, r3, addr)                                          \
    asm volatile("ldmatrix.sync.aligned.m8n8.x4.shared.b16 {%0,%1,%2,%3}, [%4];" \
                 : "=r"(r0), "=r"(r1), "=r"(r2), "=r"(r3) : "r"(addr))

static __device__ __forceinline__ void mma16(float c[4], const uint32_t a[4],
                                             uint32_t b0, uint32_t b1) {
    asm volatile(
        "mma.sync.aligned.m16n8k16.row.col.f32.bf16.bf16.f32 "
        "{%0,%1,%2,%3}, {%4,%5,%6,%7}, {%8,%9}, {%0,%1,%2,%3};\n"
        : "+f"(c[0]), "+f"(c[1]), "+f"(c[2]), "+f"(c[3])
        : "r"(a[0]), "r"(a[1]), "r"(a[2]), "r"(a[3]), "r"(b0), "r"(b1));
}

#define CPA16(dst, src) \
    asm volatile("cp.async.cg.shared.global [%0], [%1], 16;" :: "r"(dst), "l"(src) : "memory")
#define CPA_COMMIT() asm volatile("cp.async.commit_group;" ::: "memory")
#define CPA_WAIT(n)  asm volatile("cp.async.wait_group %0;" :: "n"(n) : "memory")

static __device__ __forceinline__ float sigmoidf_(float x) {
    return 1.0f / (1.0f + __expf(-x));
}
static __device__ __forceinline__ uint32_t packbf2(float x, float y) {
    __nv_bfloat162 h = __floats2bfloat162_rn(x, y);
    return *(uint32_t*)&h;
}
// SW64 swizzle applied to a FULL byte offset (row*64 + col, col < 64).
static __device__ __forceinline__ uint32_t swz64(uint32_t b) {
    return b ^ ((b >> 3) & 0x30u);
}

// ============================================================================
// Fused convert kernel — now 2 independent float4 jobs per thread (MLP=2).
// ============================================================================
constexpr size_t NH4   = (size_t)BSZ * HH / 4;       // 4194304
constexpr size_t NU4   = (size_t)HH  * HH / 4;       // 1048576
constexpr size_t NV4   = (size_t)DD  * HH / 4;       // 53248
constexpr size_t NF4   = NH4 + NU4 + NV4;
constexpr size_t NPAD  = (size_t)(BSZ + HH) * DP;
constexpr size_t NCVT  = NF4 + NPAD;
constexpr size_t NCVT2 = (NCVT + 1) / 2;

__global__ __launch_bounds__(256) void cvt_all(
    const float4* __restrict__ hid, const float4* __restrict__ uw,
    const float4* __restrict__ vw,  const float*  __restrict__ line,
    const float*  __restrict__ ww)
{
    const size_t base = ((size_t)blockIdx.x * blockDim.x + threadIdx.x) * 2;
    #pragma unroll
    for (int q = 0; q < 2; q++) {
        const size_t i = base + q;
        if (i >= NCVT) return;
        if (i < NF4) {
            float4 v; __nv_bfloat16* dst;
            if (i < NH4)            { v = hid[i];              dst = g_hid + i * 4; }
            else if (i < NH4 + NU4) { v = uw[i - NH4];         dst = g_Uw  + (i - NH4) * 4; }
            else                    { v = vw[i - NH4 - NU4];   dst = g_Vwb + (i - NH4 - NU4) * 4; }
            uint2 o;
            o.x = packbf2(v.x, v.y);
            o.y = packbf2(v.z, v.w);
            *(uint2*)dst = o;
        } else {
            size_t j   = i - NF4;
            size_t row = j >> 7;
            int    col = (int)(j & 127);
            float v = 0.f;
            if (col < DD)
                v = (row < BSZ) ? line[row * DD + col] : ww[(row - BSZ) * DD + col];
            ((row < BSZ) ? g_line : g_Ww)[((row < BSZ) ? row : row - BSZ) * DP + col] =
                __float2bfloat16(v);
        }
    }
}

// ============================================================================
// Kernel 1 — R14 winner (~317us) with ONE change: all 12 LDSMs issued before
// the 64 MMAs (single latency exposure per iter, then uninterrupted MMA
// stream). Fragment regs 24->48; offsets use (x+32)^m == (x^m)^32 to save 6.
// Est. 124 regs; __launch_bounds__(256,2) pins the 128-reg / 2-CTA budget.
// ============================================================================
constexpr int OP1     = 128 * 64;             // 8192 B per operand per stage
constexpr int STG1    = 2 * OP1;              // 16384 B per stage
constexpr int K1_ST   = 4;
constexpr int K1_SMEM = K1_ST * STG1;         // 65536 (2 CTAs = 128KB)
constexpr int K1_NT1  = HH / 32;              // 64
constexpr int K1_NT   = K1_NT1 + DP / 32;     // 68

__global__ __launch_bounds__(256, 2) void rnn_k1(
    const float* __restrict__ U_b, const float* __restrict__ W_b,
    float* __restrict__ ht)
{
    extern __shared__ char sm1[];
    const uint32_t sb = s2u(sm1);

    const int tid  = threadIdx.x;
    const int warp = tid >> 5, lane = tid & 31;
    const int wm   = (warp >> 2) * 64;
    const int wn   = (warp & 3) * 32;
    const int grp  = lane >> 2, tig = lane & 3;
    const int lr16 = lane & 15, lh = lane >> 4;

    const int mBase = blockIdx.y * 128;
    const int nBase = blockIdx.x * 128;

    // h0 fragment offsets; h1 = h0 ^ 32 (valid: lh*16 < 32, no carry).
    uint32_t aOff[4], bOff[2];
    #pragma unroll
    for (int mt = 0; mt < 4; mt++) {
        const uint32_t rb = (uint32_t)(wm + mt * 16 + lr16) * 64;
        aOff[mt] = rb + (((uint32_t)lh * 16) ^ ((rb >> 3) & 0x30u));
    }
    #pragma unroll
    for (int p = 0; p < 2; p++) {
        const uint32_t rb = (uint32_t)(wn + p * 16 + lr16) * 64;
        bOff[p] = OP1 + rb + (((uint32_t)lh * 16) ^ ((rb >> 3) & 0x30u));
    }

    // producer (coalescing-optimal): row tid>>1, 32B half tid&1.
    const int lrow = tid >> 1;
    const int lcb  = (tid & 1) * 16;              // bf16 elems
    const __nv_bfloat16* hA = g_hid  + (size_t)(mBase + lrow) * HH + lcb;
    const __nv_bfloat16* uB = g_Uw   + (size_t)(nBase + lrow) * HH + lcb;
    const __nv_bfloat16* lA = g_line + (size_t)(mBase + lrow) * DP + lcb;
    const __nv_bfloat16* wB = g_Ww   + (size_t)(nBase + lrow) * DP + lcb;
    const uint32_t b0   = (uint32_t)lrow * 64 + (uint32_t)lcb * 2;
    const uint32_t dOf0 = swz64(b0);
    const uint32_t dOf1 = swz64(b0 + 16);

    auto issue_stage = [&](int slot, int f) {
        const uint32_t s0 = sb + slot * STG1;
        const __nv_bfloat16 *sA, *sB;
        if (f < K1_NT1) { sA = hA + f * 32;             sB = uB + f * 32; }
        else            { sA = lA + (f - K1_NT1) * 32;  sB = wB + (f - K1_NT1) * 32; }
        CPA16(s0 + dOf0,       sA);
        CPA16(s0 + dOf1,       sA + 8);
        CPA16(s0 + OP1 + dOf0, sB);
        CPA16(s0 + OP1 + dOf1, sB + 8);
    };

    float acc[4][4][4];
    #pragma unroll
    for (int i = 0; i < 4; i++)
        #pragma unroll
        for (int j = 0; j < 4; j++)
            #pragma unroll
            for (int k = 0; k < 4; k++) acc[i][j][k] = 0.f;

    #pragma unroll
    for (int s = 0; s < K1_ST - 1; s++) { issue_stage(s, s); CPA_COMMIT(); }

    for (int t = 0; t < K1_NT; t++) {
        CPA_WAIT(2);
        __syncthreads();
        if (t + K1_ST - 1 < K1_NT)
            issue_stage((t + K1_ST - 1) & (K1_ST - 1), t + K1_ST - 1);
        CPA_COMMIT();

        const int slot = t & (K1_ST - 1);
        const uint32_t stg = sb + slot * STG1;

        // ---- all fragment loads first (12 LDSM), then 64 MMAs ----
        uint32_t a[2][4][4], bm[2][2][4];
        #pragma unroll
        for (int h = 0; h < 2; h++) {
            const uint32_t hx = h * 32;
            #pragma unroll
            for (int mt = 0; mt < 4; mt++)
                LDSM4(a[h][mt][0], a[h][mt][1], a[h][mt][2], a[h][mt][3],
                      stg + (aOff[mt] ^ hx));
            #pragma unroll
            for (int p = 0; p < 2; p++)
                LDSM4(bm[h][p][0], bm[h][p][1], bm[h][p][2], bm[h][p][3],
                      stg + (bOff[p] ^ hx));
        }
        #pragma unroll
        for (int h = 0; h < 2; h++)
            #pragma unroll
            for (int mt = 0; mt < 4; mt++)
                #pragma unroll
                for (int nt = 0; nt < 4; nt++) {
                    const int p = nt >> 1, o = nt & 1;
                    mma16(acc[mt][nt], a[h][mt], bm[h][p][o], bm[h][p][o + 2]);
                }
    }

    // epilogue: bias + sigmoid -> fp32 h_t (output) + bf16 h_t (scratch)
    #pragma unroll
    for (int nt = 0; nt < 4; nt++) {
        const int cn = nBase + wn + nt * 8 + tig * 2;
        const float b0f = U_b[cn]     + W_b[cn];
        const float b1f = U_b[cn + 1] + W_b[cn + 1];
        #pragma unroll
        for (int mt = 0; mt < 4; mt++) {
            const int rm = mBase + wm + mt * 16 + grp;
            const float s00 = sigmoidf_(acc[mt][nt][0] + b0f);
            const float s01 = sigmoidf_(acc[mt][nt][1] + b1f);
            const float s10 = sigmoidf_(acc[mt][nt][2] + b0f);
            const float s11 = sigmoidf_(acc[mt][nt][3] + b1f);
            *(float2*)&ht[(size_t)rm * HH + cn]       = make_float2(s00, s01);
            *(float2*)&ht[(size_t)(rm + 8) * HH + cn] = make_float2(s10, s11);
            *(uint32_t*)&g_htb[(size_t)rm * HH + cn]       = packbf2(s00, s01);
            *(uint32_t*)&g_htb[(size_t)(rm + 8) * HH + cn] = packbf2(s10, s11);
        }
    }
}

// ============================================================================
// Kernel 2 — UNCHANGED from R15 (best measured): M=32/CTA, grid 256,
// 256 threads / 8 warps, 6-stage cp.async, fused log-softmax epilogue.
// ============================================================================
constexpr int RS2      = 40;
constexpr int K2_A_B   = 32  * RS2 * 2;           // 2560 B
constexpr int K2_B_B   = 104 * RS2 * 2;           // 8320 B
constexpr int K2_STAGE = K2_A_B + K2_B_B;         // 10880
constexpr int K2_ST    = 6;
constexpr int K2_SMEM  = K2_ST * K2_STAGE;        // 65280
constexpr int K2_NT    = HH / 32;                 // 64

__global__ __launch_bounds__(256) void rnn_k2(
    const float* __restrict__ V_b, float* __restrict__ pred)
{
    extern __shared__ char sm2[];
    const uint32_t sb = s2u(sm2);
    const int tid  = threadIdx.x;
    const int warp = tid >> 5, lane = tid & 31;
    const int wm   = (warp & 1) * 16;
    const int ng   = warp >> 1;
    const int grp  = lane >> 2, tig = lane & 3;

    const int nsplit[5] = {0, 4, 7, 10, 13};
    const int nbase = nsplit[ng];
    const int ncnt  = nsplit[ng + 1] - nbase;     // 4,3,3,3

    const int mBase = blockIdx.x * 32;
    const __nv_bfloat16* Ap = g_htb + (size_t)mBase * HH;

    float acc[4][4];
    #pragma unroll
    for (int i = 0; i < 4; i++)
        #pragma unroll
        for (int j = 0; j < 4; j++) acc[i][j] = 0.f;

    auto load_stage = [&](int s, int k0) {
        const uint32_t base = sb + s * K2_STAGE;
        if (tid < 128) {
            const int row = tid >> 2, cc = (tid & 3) * 8;
            CPA16(base + (uint32_t)(row * RS2 + cc) * 2,
                  Ap + (size_t)row * HH + k0 + cc);
        }
        #pragma unroll
        for (int i = 0; i < 2; i++) {
            const int c = tid + i * 256;
            if (c < 416) {
                const int row = c >> 2, cc = (c & 3) * 8;
                CPA16(base + K2_A_B + (uint32_t)(row * RS2 + cc) * 2,
                      g_Vwb + (size_t)row * HH + k0 + cc);
            }
        }
    };

    #pragma unroll
    for (int s = 0; s < K2_ST - 1; s++) { load_stage(s, s * 32); CPA_COMMIT(); }

    int slot = 0;
    for (int t = 0; t < K2_NT; t++) {
        CPA_WAIT(4);
        __syncthreads();
        if (t + K2_ST - 1 < K2_NT) {
            int rs = slot + K2_ST - 1; if (rs >= K2_ST) rs -= K2_ST;
            load_stage(rs, (t + K2_ST - 1) * 32);
        }
        CPA_COMMIT();

        const __nv_bfloat16* As = (const __nv_bfloat16*)(sm2 + slot * K2_STAGE);
        const __nv_bfloat16* Bs = (const __nv_bfloat16*)(sm2 + slot * K2_STAGE + K2_A_B);
        #pragma unroll
        for (int kk = 0; kk < 32; kk += 16) {
            uint32_t a[4];
            const int r0 = wm + grp;
            a[0] = *(const uint32_t*)&As[r0 * RS2 + kk + 2 * tig];
            a[1] = *(const uint32_t*)&As[(r0 + 8) * RS2 + kk + 2 * tig];
            a[2] = *(const uint32_t*)&As[r0 * RS2 + kk + 2 * tig + 8];
            a[3] = *(const uint32_t*)&As[(r0 + 8) * RS2 + kk + 2 * tig + 8];
            #pragma unroll
            for (int nt = 0; nt < 4; nt++) {
                if (nt < ncnt) {
                    const int c0 = (nbase + nt) * 8 + grp;
                    const uint32_t blo = *(const uint32_t*)&Bs[c0 * RS2 + kk + 2 * tig];
                    const uint32_t bhi = *(const uint32_t*)&Bs[c0 * RS2 + kk + 2 * tig + 8];
                    mma16(acc[nt], a, blo, bhi);
                }
            }
        }
        if (++slot == K2_ST) slot = 0;
    }

    // -------- fused epilogue: bias + segmented log-softmax ------------------
    __syncthreads();
    float* st   = (float*)sm2;            // [32][108]
    float* segm = st + 32 * 108;
    float* segl = segm + 320;

    #pragma unroll
    for (int nt = 0; nt < 4; nt++) {
        if (nt < ncnt) {
            const int cn = (nbase + nt) * 8 + tig * 2;
            const float b0 = V_b[cn], b1 = V_b[cn + 1];
            const int r = wm + grp;
            st[r * 108 + cn]           = acc[nt][0] + b0;
            st[r * 108 + cn + 1]       = acc[nt][1] + b1;
            st[(r + 8) * 108 + cn]     = acc[nt][2] + b0;
            st[(r + 8) * 108 + cn + 1] = acc[nt][3] + b1;
        }
    }
    __syncthreads();

    const int bnd[11] = {0, 13, 26, 39, 48, 52, 65, 78, 91, 100, 104};
    if (tid < 32) {
        const float* row = st + tid * 108;
        #pragma unroll
        for (int s = 0; s < 10; s++) {
            float m = -1e30f;
            for (int j = bnd[s]; j < bnd[s + 1]; j++) m = fmaxf(m, row[j]);
            float sum = 0.f;
            for (int j = bnd[s]; j < bnd[s + 1]; j++) sum += expf(row[j] - m);
            segm[tid * 10 + s] = m;
            segl[tid * 10 + s] = logf(sum);
        }
    }
    __syncthreads();

    if (tid < 104) {
        int sg = 0;
        #pragma unroll
        for (int i = 1; i < 10; i++)
            if (tid >= bnd[i]) sg = i;
        for (int r = 0; r < 32; r++)
            pred[(size_t)(mBase + r) * DD + tid] =
                st[r * 108 + tid] - segm[r * 10 + sg] - segl[r * 10 + sg];
    }
}

// ============================================================================
// Launch
// ============================================================================
extern "C" void kernel_launch(void* const* d_in, const int* in_sizes, int n_in,
                              void* d_out, int out_size)
{
    const float* line   = (const float*)d_in[0];
    const float* hidden = (const float*)d_in[1];
    const float* U_w    = (const float*)d_in[2];
    const float* U_b    = (const float*)d_in[3];
    const float* W_w    = (const float*)d_in[4];
    const float* W_b    = (const float*)d_in[5];
    const float* V_w    = (const float*)d_in[6];
    const float* V_b    = (const float*)d_in[7];

    float* out  = (float*)d_out;
    float* pred = out;                          // [8192, 104]
    float* ht   = out + (size_t)BSZ * DD;       // [8192, 2048]

    cudaFuncSetAttribute(rnn_k1, cudaFuncAttributeMaxDynamicSharedMemorySize, K1_SMEM);
    cudaFuncSetAttribute(rnn_k2, cudaFuncAttributeMaxDynamicSharedMemorySize, K2_SMEM);

    const int gcv = (int)((NCVT2 + 255) / 256);
    cvt_all<<<gcv, 256>>>((const float4*)hidden, (const float4*)U_w,
                          (const float4*)V_w, line, W_w);

    dim3 g1(HH / 128, BSZ / 128);               // (16, 64)
    rnn_k1<<<g1, 256, K1_SMEM>>>(U_b, W_b, ht);
    rnn_k2<<<BSZ / 32, 256, K2_SMEM>>>(V_b, pred);
}